// round 9
// baseline (speedup 1.0000x reference)
#include <cuda_runtime.h>
#include <mma.h>
using namespace nvcuda;

#define BB 4
#define CC 192
#define HWP 4096
#define KIM 1728
#define LEAK 0.01f
typedef long long ll;

// ---------------- device scratch (R2-identical set) ----------------
__device__ float g_col [(size_t)BB * KIM * HWP];
__device__ float g_tmp [(size_t)BB * CC * HWP];
__device__ float g_f1  [(size_t)BB * CC * HWP];
__device__ float g_f2  [(size_t)BB * CC * HWP];
__device__ float g_corr[(size_t)BB * HWP * HWP];
__device__ float g_corr1[(size_t)BB * 1024 * 1024];
__device__ float g_corr2[(size_t)BB * 256 * 256];

// ---------------- im2col (R2 verbatim) ----------------
__global__ __launch_bounds__(256)
void im2col4_k(const float* __restrict__ x, float* __restrict__ col) {
    int idx = blockIdx.x * 256 + threadIdx.x;
    const int total = BB * KIM * 1024;
    if (idx >= total) return;
    int p4 = (idx & 1023) << 2;
    int ck = (idx >> 10) % KIM;
    int b  = idx / (1024 * KIM);
    int ci = ck / 9, k = ck % 9;
    int row = (p4 >> 6) + (k / 3) - 1;
    int c0  = (p4 & 63) + (k % 3) - 1;
    float4 v = make_float4(0.f, 0.f, 0.f, 0.f);
    if (row >= 0 && row < 64) {
        const float* xr = x + (((ll)b * CC + ci) << 12) + (row << 6);
        v.x = (c0 >= 0)     ? xr[c0]     : 0.f;
        v.y = xr[c0 + 1];
        v.z = xr[c0 + 2];
        v.w = (c0 + 3 < 64) ? xr[c0 + 3] : 0.f;
    }
    reinterpret_cast<float4*>(col)[idx] = v;
}

// ---------------- tf32 split ----------------
__device__ __forceinline__ void t32(float v, float& h, float& l) {
    h = wmma::__float_to_tf32(v);
    l = wmma::__float_to_tf32(v - h);
}

// ===========================================================================
// gw: C[m][n] = sum_k A(m,k)*B(n,k);  A row-major [M][K] (lda).
//   BN=true : B is [K][N] (n contiguous, ldb = global N)   [im2col buffer]
//   BN=false: B is [N][K] (k contiguous, ldb = row stride) [ref / o1 / o2]
// tf32 3-term split (hi*hi + hi*lo + lo*hi), fp32 accumulate.
// MODE 1: leaky(bias[m]); 2: +resid; 3: plain, TRANSPOSED store C[n][m].
// Block tile TM x TN, 256 threads, warp tile 32x32, K-chunk 16, dbl-buffered.
// ===========================================================================
template<int TM, int TN, bool BN, int MODE>
__global__ __launch_bounds__(256)
void gw(const float* __restrict__ A, ll abat, int lda,
        const float* __restrict__ B, ll bbat, int ldb,
        int K, const float* __restrict__ bias,
        const float* __restrict__ resid, ll rbat,
        float* __restrict__ C, ll cbat, int ldc)
{
    constexpr int WMW = TM / 32;                 // warps along m
    constexpr int AFL = TM * 20;                 // floats per A plane
    constexpr int BFL = BN ? 16 * (TN + 4) : TN * 20;
    constexpr int STFL = 2 * (AFL + BFL);        // floats per stage (hi+lo)
    constexpr int TLD = TN + 4;
    constexpr int NAI = (TM * 4) / 256;          // A float4s per thread
    constexpr int NBI = (BN ? 4 * TN : TN * 4) / 256;

    extern __shared__ float sm[];
    const int tid = threadIdx.x, w = tid >> 5;
    const int wm = w % WMW, wn = w / WMW;
    const int n0 = blockIdx.x * TN, m0 = blockIdx.y * TM, b = blockIdx.z;

    const float* Ab = A + (ll)b * abat;
    const float* Bb = B + (ll)b * bbat;
    const int NC = K >> 4;

    float4 ra[NAI], rb[NBI];

    auto fetch = [&](int c) {
#pragma unroll
        for (int i = 0; i < NAI; i++) {
            int it = tid + i * 256;
            int r = it >> 2, u = it & 3;
            ra[i] = *reinterpret_cast<const float4*>(Ab + (ll)(m0 + r) * lda + c * 16 + u * 4);
        }
#pragma unroll
        for (int i = 0; i < NBI; i++) {
            int it = tid + i * 256;
            if (BN) {
                int kk = it / (TN / 4), nq = it % (TN / 4);
                rb[i] = *reinterpret_cast<const float4*>(Bb + (ll)(c * 16 + kk) * ldb + n0 + nq * 4);
            } else {
                int r = it >> 2, u = it & 3;
                rb[i] = *reinterpret_cast<const float4*>(Bb + (ll)(n0 + r) * ldb + c * 16 + u * 4);
            }
        }
    };
    auto stash = [&](int s) {
        float* Ah = sm + s * STFL;
        float* Al = Ah + AFL;
        float* Bh = Al + AFL;
        float* Bl = Bh + BFL;
#pragma unroll
        for (int i = 0; i < NAI; i++) {
            int it = tid + i * 256;
            int r = it >> 2, u = it & 3;
            int o = r * 20 + u * 4;
            t32(ra[i].x, Ah[o], Al[o]);     t32(ra[i].y, Ah[o+1], Al[o+1]);
            t32(ra[i].z, Ah[o+2], Al[o+2]); t32(ra[i].w, Ah[o+3], Al[o+3]);
        }
#pragma unroll
        for (int i = 0; i < NBI; i++) {
            int it = tid + i * 256;
            int o;
            if (BN) { int kk = it / (TN / 4), nq = it % (TN / 4); o = kk * (TN + 4) + nq * 4; }
            else    { int r = it >> 2, u = it & 3;                o = r * 20 + u * 4; }
            t32(rb[i].x, Bh[o], Bl[o]);     t32(rb[i].y, Bh[o+1], Bl[o+1]);
            t32(rb[i].z, Bh[o+2], Bl[o+2]); t32(rb[i].w, Bh[o+3], Bl[o+3]);
        }
    };

    wmma::fragment<wmma::accumulator, 16, 16, 8, float> acc[2][2];
#pragma unroll
    for (int i = 0; i < 2; i++)
#pragma unroll
        for (int j = 0; j < 2; j++) wmma::fill_fragment(acc[i][j], 0.f);

    fetch(0); stash(0); __syncthreads();

    for (int c = 0; c < NC; c++) {
        const bool more = (c + 1 < NC);
        if (more) fetch(c + 1);

        const float* Ah = sm + (c & 1) * STFL;
        const float* Al = Ah + AFL;
        const float* Bh = Al + AFL;
        const float* Bl = Bh + BFL;
#pragma unroll
        for (int ks = 0; ks < 2; ks++) {
            wmma::fragment<wmma::matrix_a, 16, 16, 8, wmma::precision::tf32, wmma::row_major> fah[2], fal[2];
#pragma unroll
            for (int i = 0; i < 2; i++) {
                wmma::load_matrix_sync(fah[i], Ah + (wm * 32 + i * 16) * 20 + ks * 8, 20);
                wmma::load_matrix_sync(fal[i], Al + (wm * 32 + i * 16) * 20 + ks * 8, 20);
            }
            if (BN) {
                wmma::fragment<wmma::matrix_b, 16, 16, 8, wmma::precision::tf32, wmma::row_major> fbh, fbl;
#pragma unroll
                for (int j = 0; j < 2; j++) {
                    wmma::load_matrix_sync(fbh, Bh + ks * 8 * (TN + 4) + wn * 32 + j * 16, TN + 4);
                    wmma::load_matrix_sync(fbl, Bl + ks * 8 * (TN + 4) + wn * 32 + j * 16, TN + 4);
#pragma unroll
                    for (int i = 0; i < 2; i++) {
                        wmma::mma_sync(acc[i][j], fah[i], fbh, acc[i][j]);
                        wmma::mma_sync(acc[i][j], fah[i], fbl, acc[i][j]);
                        wmma::mma_sync(acc[i][j], fal[i], fbh, acc[i][j]);
                    }
                }
            } else {
                wmma::fragment<wmma::matrix_b, 16, 16, 8, wmma::precision::tf32, wmma::col_major> fbh, fbl;
#pragma unroll
                for (int j = 0; j < 2; j++) {
                    wmma::load_matrix_sync(fbh, Bh + (wn * 32 + j * 16) * 20 + ks * 8, 20);
                    wmma::load_matrix_sync(fbl, Bl + (wn * 32 + j * 16) * 20 + ks * 8, 20);
#pragma unroll
                    for (int i = 0; i < 2; i++) {
                        wmma::mma_sync(acc[i][j], fah[i], fbh, acc[i][j]);
                        wmma::mma_sync(acc[i][j], fah[i], fbl, acc[i][j]);
                        wmma::mma_sync(acc[i][j], fal[i], fbh, acc[i][j]);
                    }
                }
            }
        }
        if (more) stash((c + 1) & 1);
        __syncthreads();
    }

    // epilogue via smem tile T[TM][TLD]
    float* T = sm;
#pragma unroll
    for (int i = 0; i < 2; i++)
#pragma unroll
        for (int j = 0; j < 2; j++)
            wmma::store_matrix_sync(T + (wm * 32 + i * 16) * TLD + wn * 32 + j * 16,
                                    acc[i][j], TLD, wmma::mem_row_major);
    __syncthreads();

    if (MODE <= 2) {
        for (int idx = tid; idx < TM * TN; idx += 256) {
            int row = idx / TN, col = idx - row * TN;
            float v = T[row * TLD + col] + bias[m0 + row];
            v = v > 0.f ? v : LEAK * v;
            if (MODE == 2)
                v += resid[(ll)b * rbat + (ll)(m0 + row) * ldc + n0 + col];
            C[(ll)b * cbat + (ll)(m0 + row) * ldc + n0 + col] = v;
        }
    } else {
        for (int idx = tid; idx < TM * TN; idx += 256) {
            int row = idx % TM, col = idx / TM;
            C[(ll)b * cbat + (ll)(n0 + col) * ldc + m0 + row] = T[row * TLD + col];
        }
    }
}

// ===========================================================================
// gx: corr[q][r] = sum_c f1[c][q]*f2[c][r].  f1,f2: [C][HW] fp32 (m/n contig).
// 128x128 tile, warps 4x2 (tile 32x64), As[k][m]/Bs[k][n] smem, tf32 split.
// ===========================================================================
__global__ __launch_bounds__(256)
void gx(const float* __restrict__ A, const float* __restrict__ B, float* __restrict__ C)
{
    constexpr int PFL = 16 * 132;       // floats per plane
    constexpr int STFL = 4 * PFL;       // Ah,Al,Bh,Bl per stage
    extern __shared__ float sm[];
    const int tid = threadIdx.x, w = tid >> 5;
    const int wm = w % 4, wn = w / 4;
    const int n0 = blockIdx.x << 7, m0 = blockIdx.y << 7, b = blockIdx.z;
    const float* Ab = A + (ll)b * (CC * HWP);
    const float* Bb = B + (ll)b * (CC * HWP);

    float4 rA[2], rB[2];
    auto fetch = [&](int c) {
#pragma unroll
        for (int i = 0; i < 2; i++) {
            int it = tid + i * 256;
            int kk = it >> 5, mq = it & 31;
            rA[i] = *reinterpret_cast<const float4*>(Ab + (ll)(c * 16 + kk) * HWP + m0 + mq * 4);
            rB[i] = *reinterpret_cast<const float4*>(Bb + (ll)(c * 16 + kk) * HWP + n0 + mq * 4);
        }
    };
    auto stash = [&](int s) {
        float* Ah = sm + s * STFL; float* Al = Ah + PFL;
        float* Bh = Al + PFL;      float* Bl = Bh + PFL;
#pragma unroll
        for (int i = 0; i < 2; i++) {
            int it = tid + i * 256;
            int kk = it >> 5, mq = it & 31;
            int o = kk * 132 + mq * 4;
            t32(rA[i].x, Ah[o], Al[o]);     t32(rA[i].y, Ah[o+1], Al[o+1]);
            t32(rA[i].z, Ah[o+2], Al[o+2]); t32(rA[i].w, Ah[o+3], Al[o+3]);
            t32(rB[i].x, Bh[o], Bl[o]);     t32(rB[i].y, Bh[o+1], Bl[o+1]);
            t32(rB[i].z, Bh[o+2], Bl[o+2]); t32(rB[i].w, Bh[o+3], Bl[o+3]);
        }
    };

    wmma::fragment<wmma::accumulator, 16, 16, 8, float> acc[2][4];
#pragma unroll
    for (int i = 0; i < 2; i++)
#pragma unroll
        for (int j = 0; j < 4; j++) wmma::fill_fragment(acc[i][j], 0.f);

    fetch(0); stash(0); __syncthreads();

    const int NC = CC >> 4;   // 12
    for (int c = 0; c < NC; c++) {
        const bool more = (c + 1 < NC);
        if (more) fetch(c + 1);
        const float* Ah = sm + (c & 1) * STFL; const float* Al = Ah + PFL;
        const float* Bh = Al + PFL;            const float* Bl = Bh + PFL;
#pragma unroll
        for (int ks = 0; ks < 2; ks++) {
            wmma::fragment<wmma::matrix_a, 16, 16, 8, wmma::precision::tf32, wmma::col_major> fah[2], fal[2];
#pragma unroll
            for (int i = 0; i < 2; i++) {
                wmma::load_matrix_sync(fah[i], Ah + ks * 8 * 132 + wm * 32 + i * 16, 132);
                wmma::load_matrix_sync(fal[i], Al + ks * 8 * 132 + wm * 32 + i * 16, 132);
            }
#pragma unroll
            for (int j = 0; j < 4; j++) {
                wmma::fragment<wmma::matrix_b, 16, 16, 8, wmma::precision::tf32, wmma::row_major> fbh, fbl;
                wmma::load_matrix_sync(fbh, Bh + ks * 8 * 132 + wn * 64 + j * 16, 132);
                wmma::load_matrix_sync(fbl, Bl + ks * 8 * 132 + wn * 64 + j * 16, 132);
#pragma unroll
                for (int i = 0; i < 2; i++) {
                    wmma::mma_sync(acc[i][j], fah[i], fbh, acc[i][j]);
                    wmma::mma_sync(acc[i][j], fah[i], fbl, acc[i][j]);
                    wmma::mma_sync(acc[i][j], fal[i], fbh, acc[i][j]);
                }
            }
        }
        if (more) stash((c + 1) & 1);
        __syncthreads();
    }

    float* Cb = C + (ll)b * ((ll)HWP * HWP);
#pragma unroll
    for (int i = 0; i < 2; i++)
#pragma unroll
        for (int j = 0; j < 4; j++)
            wmma::store_matrix_sync(Cb + (ll)(m0 + wm * 32 + i * 16) * HWP + n0 + wn * 64 + j * 16,
                                    acc[i][j], HWP, wmma::mem_row_major);
}

// ---------------- softmax (R2 verbatim, fp32 in-place) ----------------
__device__ __forceinline__ float wmaxf(float v) {
#pragma unroll
    for (int o = 16; o > 0; o >>= 1) v = fmaxf(v, __shfl_xor_sync(0xffffffffu, v, o));
    return v;
}
__device__ __forceinline__ float wsumf(float v) {
#pragma unroll
    for (int o = 16; o > 0; o >>= 1) v += __shfl_xor_sync(0xffffffffu, v, o);
    return v;
}
__global__ __launch_bounds__(256)
void softmax4_k(float* __restrict__ S) {
    float4* p = reinterpret_cast<float4*>(S + (ll)blockIdx.x * HWP);
    const int tid = threadIdx.x;
    const int lane = tid & 31, wid = tid >> 5;
    float4 v[4]; float mx = -3.0e38f;
#pragma unroll
    for (int i = 0; i < 4; i++) {
        v[i] = p[tid + 256 * i];
        mx = fmaxf(mx, fmaxf(fmaxf(v[i].x, v[i].y), fmaxf(v[i].z, v[i].w)));
    }
    __shared__ float red[8];
    mx = wmaxf(mx);
    if (lane == 0) red[wid] = mx;
    __syncthreads();
    if (wid == 0) { float t = (lane < 8) ? red[lane] : -3.0e38f; t = wmaxf(t); if (lane == 0) red[0] = t; }
    __syncthreads();
    mx = red[0];
    __syncthreads();
    float s = 0.f;
#pragma unroll
    for (int i = 0; i < 4; i++) {
        v[i].x = __expf(v[i].x - mx); v[i].y = __expf(v[i].y - mx);
        v[i].z = __expf(v[i].z - mx); v[i].w = __expf(v[i].w - mx);
        s += v[i].x + v[i].y + v[i].z + v[i].w;
    }
    s = wsumf(s);
    if (lane == 0) red[wid] = s;
    __syncthreads();
    if (wid == 0) { float t = (lane < 8) ? red[lane] : 0.f; t = wsumf(t); if (lane == 0) red[0] = t; }
    __syncthreads();
    const float inv = 1.f / red[0];
#pragma unroll
    for (int i = 0; i < 4; i++) {
        v[i].x *= inv; v[i].y *= inv; v[i].z *= inv; v[i].w *= inv;
        p[tid + 256 * i] = v[i];
    }
}

// ---------------- pool (R2 verbatim, fp32) ----------------
__global__ __launch_bounds__(256)
void pool2_k(const float* __restrict__ in, float* __restrict__ out, int g) {
    const int g2 = g >> 1;
    const int G2 = g2 * g2;
    const int halfP = G2 >> 1;
    const ll total = (ll)BB * G2 * halfP;
    ll idx = (ll)blockIdx.x * 256 + threadIdx.x;
    if (idx >= total) return;
    int t  = (int)(idx % halfP);
    int qp = (int)((idx / halfP) % G2);
    int b  = (int)(idx / ((ll)halfP * G2));
    const int Rh  = (2 * t) / g2;
    const int Rw0 = (2 * t) % g2;
    const int Qh = qp / g2, Qw = qp % g2;
    const ll G = (ll)g * g;
    const float* base = in + (ll)b * G * G;
    float s0 = 0.f, s1 = 0.f;
#pragma unroll
    for (int i = 0; i < 2; i++)
#pragma unroll
        for (int j = 0; j < 2; j++) {
            const float* qrow = base + ((ll)((2 * Qh + i) * g + 2 * Qw + j)) * G;
#pragma unroll
            for (int u = 0; u < 2; u++) {
                const float2* rp = reinterpret_cast<const float2*>(
                    qrow + (ll)(2 * Rh + u) * g + 2 * Rw0);
                float2 x0 = rp[0], x1 = rp[1];
                s0 += x0.x + x0.y;
                s1 += x1.x + x1.y;
            }
        }
    float2 o = make_float2(s0 * (1.f / 16.f), s1 * (1.f / 16.f));
    *reinterpret_cast<float2*>(out + ((ll)b * G2 + qp) * G2 + 2 * t) = o;
}

// ---------------- host ----------------
#define GS(p, s) cudaGetSymbolAddress((void**)&p, s)

extern "C" void kernel_launch(void* const* d_in, const int* in_sizes, int n_in,
                              void* d_out, int out_size)
{
    const float* fd1 = (const float*)d_in[0];
    const float* fd2 = (const float*)d_in[1];
    const float* ref = (const float*)d_in[2];
    const float* o1  = (const float*)d_in[3];
    const float* o2  = (const float*)d_in[4];
    const float* tw1 = (const float*)d_in[5];
    const float* tb1 = (const float*)d_in[6];
    const float* tw2 = (const float*)d_in[7];
    const float* tb2 = (const float*)d_in[8];
    const float* pw1 = (const float*)d_in[9];
    const float* pb1 = (const float*)d_in[10];
    const float* pw2 = (const float*)d_in[11];
    const float* pb2 = (const float*)d_in[12];
    float* out = (float*)d_out;

    float *col, *tmp, *f1, *f2, *corr, *corr1, *corr2;
    GS(col, g_col); GS(tmp, g_tmp); GS(f1, g_f1); GS(f2, g_f2);
    GS(corr, g_corr); GS(corr1, g_corr1); GS(corr2, g_corr2);

    // dynamic smem: conv 54,272 B; transposed-attn 61,440 B; gx 67,584 B
    const int SMCONV = 2 * 2 * (64 * 20 + 16 * 132) * 4;
    const int SMT    = 2 * 2 * (128 * 20 + 64 * 20) * 4;
    const int SMX    = 2 * 4 * (16 * 132) * 4;
    cudaFuncSetAttribute(gw<64,128,true,1>,  cudaFuncAttributeMaxDynamicSharedMemorySize, SMCONV);
    cudaFuncSetAttribute(gw<64,128,true,2>,  cudaFuncAttributeMaxDynamicSharedMemorySize, SMCONV);
    cudaFuncSetAttribute(gw<128,64,false,3>, cudaFuncAttributeMaxDynamicSharedMemorySize, SMT);
    cudaFuncSetAttribute(gx,                 cudaFuncAttributeMaxDynamicSharedMemorySize, SMX);

    const ll featB = (ll)CC * HWP;
    const ll colB  = (ll)KIM * HWP;
    const int imGrid = (BB * KIM * 1024 + 255) / 256;
    const dim3 convG(32, 3, BB);

    // theta resblock
    im2col4_k<<<imGrid, 256>>>(fd1, col);
    gw<64,128,true,1><<<convG, 256, SMCONV>>>(tw1, 0, KIM, col, colB, HWP, KIM,
        tb1, nullptr, 0, tmp, featB, HWP);
    im2col4_k<<<imGrid, 256>>>(tmp, col);
    gw<64,128,true,2><<<convG, 256, SMCONV>>>(tw2, 0, KIM, col, colB, HWP, KIM,
        tb2, fd1, featB, f1, featB, HWP);
    // phi resblock
    im2col4_k<<<imGrid, 256>>>(fd2, col);
    gw<64,128,true,1><<<convG, 256, SMCONV>>>(pw1, 0, KIM, col, colB, HWP, KIM,
        pb1, nullptr, 0, tmp, featB, HWP);
    im2col4_k<<<imGrid, 256>>>(tmp, col);
    gw<64,128,true,2><<<convG, 256, SMCONV>>>(pw2, 0, KIM, col, colB, HWP, KIM,
        pb2, fd2, featB, f2, featB, HWP);

    // corr = f1^T f2
    gx<<<dim3(32, 32, BB), 256, SMX>>>(f1, f2, corr);
    softmax4_k<<<BB * HWP, 256>>>(corr);

    // out0: A=corr [q][r] (M=4096), B=ref [c][r] (N=192) -> transposed store [c][q]
    gw<128,64,false,3><<<dim3(3, 32, BB), 256, SMT>>>(corr, (ll)HWP * HWP, HWP,
        ref, featB, HWP, HWP, nullptr, nullptr, 0, out, featB, HWP);

    // level 1
    {
        const ll total = (ll)BB * 1024 * 512;
        pool2_k<<<(int)((total + 255) / 256), 256>>>(corr, corr1, 64);
        gw<128,64,false,3><<<dim3(3, 8, BB), 256, SMT>>>(corr1, (ll)1024 * 1024, 1024,
            o1, (ll)CC * 1024, 1024, 1024, nullptr, nullptr, 0,
            out + (ll)BB * featB, (ll)CC * 1024, 1024);
    }
    // level 2
    {
        const ll total = (ll)BB * 256 * 128;
        pool2_k<<<(int)((total + 255) / 256), 256>>>(corr1, corr2, 32);
        gw<128,64,false,3><<<dim3(3, 2, BB), 256, SMT>>>(corr2, (ll)256 * 256, 256,
            o2, (ll)CC * 256, 256, 256, nullptr, nullptr, 0,
            out + (ll)BB * featB + (ll)BB * CC * 1024, (ll)CC * 256, 256);
    }

    (void)in_sizes; (void)n_in; (void)out_size;
}

// round 10
// speedup vs baseline: 1.2780x; 1.2780x over previous
#include <cuda_runtime.h>
#include <cuda_bf16.h>
#include <mma.h>
using namespace nvcuda;

#define BB 4
#define CC 192
#define HWP 4096
#define KIM 1728
#define LEAK 0.01f
typedef long long ll;
typedef __nv_bfloat16 bf;

// ---------------- device scratch ----------------
__device__ float g_tmp [(size_t)BB * CC * HWP];
__device__ float g_f1  [(size_t)BB * CC * HWP];
__device__ float g_f2  [(size_t)BB * CC * HWP];
__device__ float g_corr[(size_t)BB * HWP * HWP];
__device__ float g_corr1[(size_t)BB * 1024 * 1024];
__device__ float g_corr2[(size_t)BB * 256 * 256];

// ---------------- tf32 / bf16 splits ----------------
__device__ __forceinline__ void t32(float v, float& h, float& l) {
    h = wmma::__float_to_tf32(v);
    l = wmma::__float_to_tf32(v - h);
}
__device__ __forceinline__ void b16(float v, bf& h, bf& l) {
    h = __float2bfloat16(v);
    l = __float2bfloat16(v - __bfloat162float(h));
}

// ===========================================================================
// gw: tf32 3-term conv GEMM. C[m][n] = sum_k A(m,k)*B(n,k).
//   A: weights [M][K] row-major (lda=K). B: implicit im2col from features
//   [C][64][64] (k = ci*9+kp, n = pixel). KC=16, dbl-buffered, 2 CTAs/SM.
// MODE 1: leaky(bias[m]); 2: +resid (read [C][HWP] fp32).
// TM=64, TN=128, 8 warps (2m x 4n), warp tile 32x32.
// ===========================================================================
template<int MODE>
__global__ __launch_bounds__(256, 2)
void gw(const float* __restrict__ A, int lda,
        const float* __restrict__ X, ll xbat,
        int K, const float* __restrict__ bias,
        const float* __restrict__ resid, ll rbat,
        float* __restrict__ C, ll cbat, int ldc)
{
    constexpr int TM = 64, TN = 128;
    constexpr int AFL = TM * 20;            // floats per A plane
    constexpr int BFL = 16 * (TN + 4);
    constexpr int STFL = 2 * (AFL + BFL);
    constexpr int TLD = TN + 4;

    extern __shared__ float sm[];
    const int tid = threadIdx.x, w = tid >> 5;
    const int wm = w & 1, wn = w >> 1;      // 2 warps m, 4 warps n
    const int n0 = blockIdx.x * TN, m0 = blockIdx.y * TM, b = blockIdx.z;

    const float* Xb = X + (ll)b * xbat;
    const int NC = K >> 4;

    float4 ra, rb0, rb1;
    auto fetch = [&](int c) {
        {   // A: 64x16 tile, 1 float4/thread
            int r = tid >> 2, u = tid & 3;
            ra = *reinterpret_cast<const float4*>(A + (ll)(m0 + r) * lda + c * 16 + u * 4);
        }
#pragma unroll
        for (int i = 0; i < 2; i++) {       // B: implicit im2col, 16k x 128n
            int it = tid + i * 256;
            int kk = it >> 5, nq = it & 31;
            int kr = c * 16 + kk;
            int ci = kr / 9, kp = kr % 9;
            int n = n0 + nq * 4;
            int row = (n >> 6) + kp / 3 - 1;
            int c0  = (n & 63) + kp % 3 - 1;
            float4 v = make_float4(0.f, 0.f, 0.f, 0.f);
            if (row >= 0 && row < 64) {
                const float* xr = Xb + ((ll)ci << 12) + (row << 6);
                v.x = (c0 >= 0)     ? xr[c0]     : 0.f;
                v.y = xr[c0 + 1];
                v.z = xr[c0 + 2];
                v.w = (c0 + 3 < 64) ? xr[c0 + 3] : 0.f;
            }
            if (i == 0) rb0 = v; else rb1 = v;
        }
    };
    auto stash = [&](int s) {
        float* Ah = sm + s * STFL;
        float* Al = Ah + AFL;
        float* Bh = Al + AFL;
        float* Bl = Bh + BFL;
        {
            int r = tid >> 2, u = tid & 3;
            int o = r * 20 + u * 4;
            t32(ra.x, Ah[o], Al[o]);     t32(ra.y, Ah[o+1], Al[o+1]);
            t32(ra.z, Ah[o+2], Al[o+2]); t32(ra.w, Ah[o+3], Al[o+3]);
        }
#pragma unroll
        for (int i = 0; i < 2; i++) {
            int it = tid + i * 256;
            int kk = it >> 5, nq = it & 31;
            int o = kk * (TN + 4) + nq * 4;
            float4 v = (i == 0) ? rb0 : rb1;
            t32(v.x, Bh[o], Bl[o]);     t32(v.y, Bh[o+1], Bl[o+1]);
            t32(v.z, Bh[o+2], Bl[o+2]); t32(v.w, Bh[o+3], Bl[o+3]);
        }
    };

    wmma::fragment<wmma::accumulator, 16, 16, 8, float> acc[2][2];
#pragma unroll
    for (int i = 0; i < 2; i++)
#pragma unroll
        for (int j = 0; j < 2; j++) wmma::fill_fragment(acc[i][j], 0.f);

    fetch(0); stash(0); __syncthreads();

    for (int c = 0; c < NC; c++) {
        const bool more = (c + 1 < NC);
        if (more) fetch(c + 1);

        const float* Ah = sm + (c & 1) * STFL;
        const float* Al = Ah + AFL;
        const float* Bh = Al + AFL;
        const float* Bl = Bh + BFL;
#pragma unroll
        for (int ks = 0; ks < 2; ks++) {
            wmma::fragment<wmma::matrix_a, 16, 16, 8, wmma::precision::tf32, wmma::row_major> fah[2], fal[2];
#pragma unroll
            for (int i = 0; i < 2; i++) {
                wmma::load_matrix_sync(fah[i], Ah + (wm * 32 + i * 16) * 20 + ks * 8, 20);
                wmma::load_matrix_sync(fal[i], Al + (wm * 32 + i * 16) * 20 + ks * 8, 20);
            }
            wmma::fragment<wmma::matrix_b, 16, 16, 8, wmma::precision::tf32, wmma::row_major> fbh, fbl;
#pragma unroll
            for (int j = 0; j < 2; j++) {
                wmma::load_matrix_sync(fbh, Bh + ks * 8 * (TN + 4) + wn * 32 + j * 16, TN + 4);
                wmma::load_matrix_sync(fbl, Bl + ks * 8 * (TN + 4) + wn * 32 + j * 16, TN + 4);
#pragma unroll
                for (int i = 0; i < 2; i++) {
                    wmma::mma_sync(acc[i][j], fah[i], fbh, acc[i][j]);
                    wmma::mma_sync(acc[i][j], fah[i], fbl, acc[i][j]);
                    wmma::mma_sync(acc[i][j], fal[i], fbh, acc[i][j]);
                }
            }
        }
        if (more) stash((c + 1) & 1);
        __syncthreads();
    }

    float* T = sm;
#pragma unroll
    for (int i = 0; i < 2; i++)
#pragma unroll
        for (int j = 0; j < 2; j++)
            wmma::store_matrix_sync(T + (wm * 32 + i * 16) * TLD + wn * 32 + j * 16,
                                    acc[i][j], TLD, wmma::mem_row_major);
    __syncthreads();

    for (int idx = tid; idx < TM * TN; idx += 256) {
        int row = idx / TN, col = idx - row * TN;
        float v = T[row * TLD + col] + bias[m0 + row];
        v = v > 0.f ? v : LEAK * v;
        if (MODE == 2)
            v += resid[(ll)b * rbat + (ll)(m0 + row) * ldc + n0 + col];
        C[(ll)b * cbat + (ll)(m0 + row) * ldc + n0 + col] = v;
    }
}

// ===========================================================================
// ga: bf16 3-term attention GEMM with TRANSPOSED store.
//   C[n][m] = sum_k A(m,k)*B(n,k).  A: corr [M][K] (lda). B: ref [N][K] (ldb).
// TM=128, TN=64, KC=32, 8 warps (4m x 2n), warp tile 32x32, 2 CTAs/SM.
// ===========================================================================
__global__ __launch_bounds__(256, 2)
void ga(const float* __restrict__ A, ll abat, int lda,
        const float* __restrict__ B, ll bbat, int ldb,
        int K, float* __restrict__ C, ll cbat, int ldc)
{
    constexpr int TM = 128, TN = 64, KC = 32;
    constexpr int SA = KC + 8;              // bf16 row stride (40 elems = 80 B)
    constexpr int AEL = TM * SA;            // bf16 elems per A plane
    constexpr int BEL = TN * SA;
    constexpr int STEL = 2 * (AEL + BEL);   // bf16 elems per stage
    constexpr int TLD = TN + 4;

    extern __shared__ float sm[];
    bf* smb = reinterpret_cast<bf*>(sm);
    const int tid = threadIdx.x, w = tid >> 5;
    const int wm = w & 3, wn = w >> 2;      // 4 warps m, 2 warps n
    const int n0 = blockIdx.x * TN, m0 = blockIdx.y * TM, b = blockIdx.z;

    const float* Ab = A + (ll)b * abat;
    const float* Bb = B + (ll)b * bbat;
    const int NC = K >> 5;

    float4 ra[4], rb[2];
    auto fetch = [&](int c) {
#pragma unroll
        for (int i = 0; i < 4; i++) {
            int it = tid + i * 256;         // < 1024
            int r = it >> 3, u = it & 7;
            ra[i] = *reinterpret_cast<const float4*>(Ab + (ll)(m0 + r) * lda + c * 32 + u * 4);
        }
#pragma unroll
        for (int i = 0; i < 2; i++) {
            int it = tid + i * 256;         // < 512
            int r = it >> 3, u = it & 7;
            rb[i] = *reinterpret_cast<const float4*>(Bb + (ll)(n0 + r) * ldb + c * 32 + u * 4);
        }
    };
    auto stash = [&](int s) {
        bf* Ah = smb + s * STEL;
        bf* Al = Ah + AEL;
        bf* Bh = Al + AEL;
        bf* Bl = Bh + BEL;
#pragma unroll
        for (int i = 0; i < 4; i++) {
            int it = tid + i * 256;
            int r = it >> 3, u = it & 7;
            int o = r * SA + u * 4;
            b16(ra[i].x, Ah[o], Al[o]);     b16(ra[i].y, Ah[o+1], Al[o+1]);
            b16(ra[i].z, Ah[o+2], Al[o+2]); b16(ra[i].w, Ah[o+3], Al[o+3]);
        }
#pragma unroll
        for (int i = 0; i < 2; i++) {
            int it = tid + i * 256;
            int r = it >> 3, u = it & 7;
            int o = r * SA + u * 4;
            b16(rb[i].x, Bh[o], Bl[o]);     b16(rb[i].y, Bh[o+1], Bl[o+1]);
            b16(rb[i].z, Bh[o+2], Bl[o+2]); b16(rb[i].w, Bh[o+3], Bl[o+3]);
        }
    };

    wmma::fragment<wmma::accumulator, 16, 16, 16, float> acc[2][2];
#pragma unroll
    for (int i = 0; i < 2; i++)
#pragma unroll
        for (int j = 0; j < 2; j++) wmma::fill_fragment(acc[i][j], 0.f);

    fetch(0); stash(0); __syncthreads();

    for (int c = 0; c < NC; c++) {
        const bool more = (c + 1 < NC);
        if (more) fetch(c + 1);

        const bf* Ah = smb + (c & 1) * STEL;
        const bf* Al = Ah + AEL;
        const bf* Bh = Al + AEL;
        const bf* Bl = Bh + BEL;
#pragma unroll
        for (int ks = 0; ks < 2; ks++) {
            wmma::fragment<wmma::matrix_a, 16, 16, 16, bf, wmma::row_major> fah[2], fal[2];
#pragma unroll
            for (int i = 0; i < 2; i++) {
                wmma::load_matrix_sync(fah[i], Ah + (wm * 32 + i * 16) * SA + ks * 16, SA);
                wmma::load_matrix_sync(fal[i], Al + (wm * 32 + i * 16) * SA + ks * 16, SA);
            }
            wmma::fragment<wmma::matrix_b, 16, 16, 16, bf, wmma::col_major> fbh, fbl;
#pragma unroll
            for (int j = 0; j < 2; j++) {
                wmma::load_matrix_sync(fbh, Bh + (wn * 32 + j * 16) * SA + ks * 16, SA);
                wmma::load_matrix_sync(fbl, Bl + (wn * 32 + j * 16) * SA + ks * 16, SA);
#pragma unroll
                for (int i = 0; i < 2; i++) {
                    wmma::mma_sync(acc[i][j], fah[i], fbh, acc[i][j]);
                    wmma::mma_sync(acc[i][j], fah[i], fbl, acc[i][j]);
                    wmma::mma_sync(acc[i][j], fal[i], fbh, acc[i][j]);
                }
            }
        }
        if (more) stash((c + 1) & 1);
        __syncthreads();
    }

    float* T = sm;
#pragma unroll
    for (int i = 0; i < 2; i++)
#pragma unroll
        for (int j = 0; j < 2; j++)
            wmma::store_matrix_sync(T + (wm * 32 + i * 16) * TLD + wn * 32 + j * 16,
                                    acc[i][j], TLD, wmma::mem_row_major);
    __syncthreads();

    for (int idx = tid; idx < TM * TN; idx += 256) {
        int row = idx % TM, col = idx / TM;     // col = channel, row = pixel
        C[(ll)b * cbat + (ll)(n0 + col) * ldc + m0 + row] = T[row * TLD + col];
    }
}

// ===========================================================================
// gx: corr[q][r] = sum_c f1[c][q]*f2[c][r] (tf32 3-term; R9 verbatim + occ 2)
// ===========================================================================
__global__ __launch_bounds__(256, 2)
void gx(const float* __restrict__ A, const float* __restrict__ B, float* __restrict__ C)
{
    constexpr int PFL = 16 * 132;
    constexpr int STFL = 4 * PFL;
    extern __shared__ float sm[];
    const int tid = threadIdx.x, w = tid >> 5;
    const int wm = w % 4, wn = w / 4;
    const int n0 = blockIdx.x << 7, m0 = blockIdx.y << 7, b = blockIdx.z;
    const float* Ab = A + (ll)b * (CC * HWP);
    const float* Bb = B + (ll)b * (CC * HWP);

    float4 rA[2], rB[2];
    auto fetch = [&](int c) {
#pragma unroll
        for (int i = 0; i < 2; i++) {
            int it = tid + i * 256;
            int kk = it >> 5, mq = it & 31;
            rA[i] = *reinterpret_cast<const float4*>(Ab + (ll)(c * 16 + kk) * HWP + m0 + mq * 4);
            rB[i] = *reinterpret_cast<const float4*>(Bb + (ll)(c * 16 + kk) * HWP + n0 + mq * 4);
        }
    };
    auto stash = [&](int s) {
        float* Ah = sm + s * STFL; float* Al = Ah + PFL;
        float* Bh = Al + PFL;      float* Bl = Bh + PFL;
#pragma unroll
        for (int i = 0; i < 2; i++) {
            int it = tid + i * 256;
            int kk = it >> 5, mq = it & 31;
            int o = kk * 132 + mq * 4;
            t32(rA[i].x, Ah[o], Al[o]);     t32(rA[i].y, Ah[o+1], Al[o+1]);
            t32(rA[i].z, Ah[o+2], Al[o+2]); t32(rA[i].w, Ah[o+3], Al[o+3]);
            t32(rB[i].x, Bh[o], Bl[o]);     t32(rB[i].y, Bh[o+1], Bl[o+1]);
            t32(rB[i].z, Bh[o+2], Bl[o+2]); t32(rB[i].w, Bh[o+3], Bl[o+3]);
        }
    };

    wmma::fragment<wmma::accumulator, 16, 16, 8, float> acc[2][4];
#pragma unroll
    for (int i = 0; i < 2; i++)
#pragma unroll
        for (int j = 0; j < 4; j++) wmma::fill_fragment(acc[i][j], 0.f);

    fetch(0); stash(0); __syncthreads();

    const int NC = CC >> 4;
    for (int c = 0; c < NC; c++) {
        const bool more = (c + 1 < NC);
        if (more) fetch(c + 1);
        const float* Ah = sm + (c & 1) * STFL; const float* Al = Ah + PFL;
        const float* Bh = Al + PFL;            const float* Bl = Bh + PFL;
#pragma unroll
        for (int ks = 0; ks < 2; ks++) {
            wmma::fragment<wmma::matrix_a, 16, 16, 8, wmma::precision::tf32, wmma::col_major> fah[2], fal[2];
#pragma unroll
            for (int i = 0; i < 2; i++) {
                wmma::load_matrix_sync(fah[i], Ah + ks * 8 * 132 + wm * 32 + i * 16, 132);
                wmma::load_matrix_sync(fal[i], Al + ks * 8 * 132 + wm * 32 + i * 16, 132);
            }
#pragma unroll
            for (int j = 0; j < 4; j++) {
                wmma::fragment<wmma::matrix_b, 16, 16, 8, wmma::precision::tf32, wmma::row_major> fbh, fbl;
                wmma::load_matrix_sync(fbh, Bh + ks * 8 * 132 + wn * 64 + j * 16, 132);
                wmma::load_matrix_sync(fbl, Bl + ks * 8 * 132 + wn * 64 + j * 16, 132);
#pragma unroll
                for (int i = 0; i < 2; i++) {
                    wmma::mma_sync(acc[i][j], fah[i], fbh, acc[i][j]);
                    wmma::mma_sync(acc[i][j], fah[i], fbl, acc[i][j]);
                    wmma::mma_sync(acc[i][j], fal[i], fbh, acc[i][j]);
                }
            }
        }
        if (more) stash((c + 1) & 1);
        __syncthreads();
    }

    float* Cb = C + (ll)b * ((ll)HWP * HWP);
#pragma unroll
    for (int i = 0; i < 2; i++)
#pragma unroll
        for (int j = 0; j < 4; j++)
            wmma::store_matrix_sync(Cb + (ll)(m0 + wm * 32 + i * 16) * HWP + n0 + wn * 64 + j * 16,
                                    acc[i][j], HWP, wmma::mem_row_major);
}

// ---------------- softmax (proven, fp32 in-place) ----------------
__device__ __forceinline__ float wmaxf(float v) {
#pragma unroll
    for (int o = 16; o > 0; o >>= 1) v = fmaxf(v, __shfl_xor_sync(0xffffffffu, v, o));
    return v;
}
__device__ __forceinline__ float wsumf(float v) {
#pragma unroll
    for (int o = 16; o > 0; o >>= 1) v += __shfl_xor_sync(0xffffffffu, v, o);
    return v;
}
__global__ __launch_bounds__(256)
void softmax4_k(float* __restrict__ S) {
    float4* p = reinterpret_cast<float4*>(S + (ll)blockIdx.x * HWP);
    const int tid = threadIdx.x;
    const int lane = tid & 31, wid = tid >> 5;
    float4 v[4]; float mx = -3.0e38f;
#pragma unroll
    for (int i = 0; i < 4; i++) {
        v[i] = p[tid + 256 * i];
        mx = fmaxf(mx, fmaxf(fmaxf(v[i].x, v[i].y), fmaxf(v[i].z, v[i].w)));
    }
    __shared__ float red[8];
    mx = wmaxf(mx);
    if (lane == 0) red[wid] = mx;
    __syncthreads();
    if (wid == 0) { float t = (lane < 8) ? red[lane] : -3.0e38f; t = wmaxf(t); if (lane == 0) red[0] = t; }
    __syncthreads();
    mx = red[0];
    __syncthreads();
    float s = 0.f;
#pragma unroll
    for (int i = 0; i < 4; i++) {
        v[i].x = __expf(v[i].x - mx); v[i].y = __expf(v[i].y - mx);
        v[i].z = __expf(v[i].z - mx); v[i].w = __expf(v[i].w - mx);
        s += v[i].x + v[i].y + v[i].z + v[i].w;
    }
    s = wsumf(s);
    if (lane == 0) red[wid] = s;
    __syncthreads();
    if (wid == 0) { float t = (lane < 8) ? red[lane] : 0.f; t = wsumf(t); if (lane == 0) red[0] = t; }
    __syncthreads();
    const float inv = 1.f / red[0];
#pragma unroll
    for (int i = 0; i < 4; i++) {
        v[i].x *= inv; v[i].y *= inv; v[i].z *= inv; v[i].w *= inv;
        p[tid + 256 * i] = v[i];
    }
}

// ---------------- pool (proven, fp32) ----------------
__global__ __launch_bounds__(256)
void pool2_k(const float* __restrict__ in, float* __restrict__ out, int g) {
    const int g2 = g >> 1;
    const int G2 = g2 * g2;
    const int halfP = G2 >> 1;
    const ll total = (ll)BB * G2 * halfP;
    ll idx = (ll)blockIdx.x * 256 + threadIdx.x;
    if (idx >= total) return;
    int t  = (int)(idx % halfP);
    int qp = (int)((idx / halfP) % G2);
    int b  = (int)(idx / ((ll)halfP * G2));
    const int Rh  = (2 * t) / g2;
    const int Rw0 = (2 * t) % g2;
    const int Qh = qp / g2, Qw = qp % g2;
    const ll G = (ll)g * g;
    const float* base = in + (ll)b * G * G;
    float s0 = 0.f, s1 = 0.f;
#pragma unroll
    for (int i = 0; i < 2; i++)
#pragma unroll
        for (int j = 0; j < 2; j++) {
            const float* qrow = base + ((ll)((2 * Qh + i) * g + 2 * Qw + j)) * G;
#pragma unroll
            for (int u = 0; u < 2; u++) {
                const float2* rp = reinterpret_cast<const float2*>(
                    qrow + (ll)(2 * Rh + u) * g + 2 * Rw0);
                float2 x0 = rp[0], x1 = rp[1];
                s0 += x0.x + x0.y;
                s1 += x1.x + x1.y;
            }
        }
    float2 o = make_float2(s0 * (1.f / 16.f), s1 * (1.f / 16.f));
    *reinterpret_cast<float2*>(out + ((ll)b * G2 + qp) * G2 + 2 * t) = o;
}

// ---------------- host ----------------
#define GS(p, s) cudaGetSymbolAddress((void**)&p, s)

extern "C" void kernel_launch(void* const* d_in, const int* in_sizes, int n_in,
                              void* d_out, int out_size)
{
    const float* fd1 = (const float*)d_in[0];
    const float* fd2 = (const float*)d_in[1];
    const float* ref = (const float*)d_in[2];
    const float* o1  = (const float*)d_in[3];
    const float* o2  = (const float*)d_in[4];
    const float* tw1 = (const float*)d_in[5];
    const float* tb1 = (const float*)d_in[6];
    const float* tw2 = (const float*)d_in[7];
    const float* tb2 = (const float*)d_in[8];
    const float* pw1 = (const float*)d_in[9];
    const float* pb1 = (const float*)d_in[10];
    const float* pw2 = (const float*)d_in[11];
    const float* pb2 = (const float*)d_in[12];
    float* out = (float*)d_out;

    float *tmp, *f1, *f2, *corr, *corr1, *corr2;
    GS(tmp, g_tmp); GS(f1, g_f1); GS(f2, g_f2);
    GS(corr, g_corr); GS(corr1, g_corr1); GS(corr2, g_corr2);

    // dynamic smem
    const int SMCONV = 2 * 2 * (64 * 20 + 16 * 132) * 4;    // 54,272
    const int SMA    = 2 * 2 * (128 * 40 + 64 * 40) * 2;    // 61,440
    const int SMX    = 2 * 4 * (16 * 132) * 4;              // 67,584
    cudaFuncSetAttribute(gw<1>, cudaFuncAttributeMaxDynamicSharedMemorySize, SMCONV);
    cudaFuncSetAttribute(gw<2>, cudaFuncAttributeMaxDynamicSharedMemorySize, SMCONV);
    cudaFuncSetAttribute(ga,    cudaFuncAttributeMaxDynamicSharedMemorySize, SMA);
    cudaFuncSetAttribute(gx,    cudaFuncAttributeMaxDynamicSharedMemorySize, SMX);

    const ll featB = (ll)CC * HWP;
    const dim3 convG(32, 3, BB);

    // theta resblock (implicit im2col)
    gw<1><<<convG, 256, SMCONV>>>(tw1, KIM, fd1, featB, KIM, tb1, nullptr, 0, tmp, featB, HWP);
    gw<2><<<convG, 256, SMCONV>>>(tw2, KIM, tmp, featB, KIM, tb2, fd1, featB, f1, featB, HWP);
    // phi resblock
    gw<1><<<convG, 256, SMCONV>>>(pw1, KIM, fd2, featB, KIM, pb1, nullptr, 0, tmp, featB, HWP);
    gw<2><<<convG, 256, SMCONV>>>(pw2, KIM, tmp, featB, KIM, pb2, fd2, featB, f2, featB, HWP);

    // corr = f1^T f2
    gx<<<dim3(32, 32, BB), 256, SMX>>>(f1, f2, corr);
    softmax4_k<<<BB * HWP, 256>>>(corr);

    // out0: A=corr [q][r] (M=4096, K=4096), B=ref [c][r] (N=192) -> [c][q]
    ga<<<dim3(3, 32, BB), 256, SMA>>>(corr, (ll)HWP * HWP, HWP,
        ref, featB, HWP, HWP, out, featB, HWP);

    // level 1
    {
        const ll total = (ll)BB * 1024 * 512;
        pool2_k<<<(int)((total + 255) / 256), 256>>>(corr, corr1, 64);
        ga<<<dim3(3, 8, BB), 256, SMA>>>(corr1, (ll)1024 * 1024, 1024,
            o1, (ll)CC * 1024, 1024, 1024,
            out + (ll)BB * featB, (ll)CC * 1024, 1024);
    }
    // level 2
    {
        const ll total = (ll)BB * 256 * 128;
        pool2_k<<<(int)((total + 255) / 256), 256>>>(corr1, corr2, 32);
        ga<<<dim3(3, 2, BB), 256, SMA>>>(corr2, (ll)256 * 256, 256,
            o2, (ll)CC * 256, 256, 256,
            out + (ll)BB * featB + (ll)BB * CC * 1024, (ll)CC * 256, 256);
    }

    (void)in_sizes; (void)n_in; (void)out_size;
}

// round 14
// speedup vs baseline: 3.5438x; 2.7729x over previous
#include <cuda_runtime.h>
#include <cuda_fp16.h>

#define BB 4
#define CC 192
#define HWP 4096
#define KIMP 1728
#define LEAK 0.01f
typedef long long ll;
typedef unsigned int u32;

// ---------------- device scratch (BASE SYMBOLS ONLY — see R13 post-mortem) ----------------
__device__ __align__(128) __half g_x1h[(size_t)BB * HWP * CC], g_x1l[(size_t)BB * HWP * CC];
__device__ __align__(128) __half g_x2h[(size_t)BB * HWP * CC], g_x2l[(size_t)BB * HWP * CC];
__device__ __align__(128) __half g_th [(size_t)BB * HWP * CC], g_tl [(size_t)BB * HWP * CC];
__device__ __align__(128) __half g_f1h[(size_t)BB * HWP * CC], g_f1l[(size_t)BB * HWP * CC];
__device__ __align__(128) __half g_f2h[(size_t)BB * HWP * CC], g_f2l[(size_t)BB * HWP * CC];
__device__ __align__(128) __half g_wallh[(size_t)4 * CC * KIMP];
__device__ __align__(128) __half g_walll[(size_t)4 * CC * KIMP];
__device__ __align__(128) float  g_corr[(size_t)BB * HWP * HWP];
__device__ __align__(128) float  g_corr1[(size_t)BB * 1024 * 1024];
__device__ __align__(128) float  g_corr2[(size_t)BB * 256 * 256];

// ---------------- helpers ----------------
__device__ __forceinline__ u32 su32(const void* p) {
    u32 a;
    asm("{ .reg .u64 t; cvta.to.shared.u64 t, %1; cvt.u32.u64 %0, t; }" : "=r"(a) : "l"(p));
    return a;
}
__device__ __forceinline__ void h16(float v, __half& h, __half& l) {
    h = __float2half(v);
    l = __float2half(v - __half2float(h));
}
__device__ __forceinline__ void ldsm4(u32 addr, u32& r0, u32& r1, u32& r2, u32& r3) {
    asm volatile("ldmatrix.sync.aligned.m8n8.x4.shared.b16 {%0,%1,%2,%3}, [%4];"
        : "=r"(r0), "=r"(r1), "=r"(r2), "=r"(r3) : "r"(addr));
}
__device__ __forceinline__ void mma16816(float* c, u32 a0, u32 a1, u32 a2, u32 a3,
                                         u32 b0, u32 b1) {
    asm volatile("mma.sync.aligned.m16n8k16.row.col.f32.f16.f16.f32 "
        "{%0,%1,%2,%3}, {%4,%5,%6,%7}, {%8,%9}, {%0,%1,%2,%3};"
        : "+f"(c[0]), "+f"(c[1]), "+f"(c[2]), "+f"(c[3])
        : "r"(a0), "r"(a1), "r"(a2), "r"(a3), "r"(b0), "r"(b1));
}

// One k16 step of a 32x32 warp tile, 3-term split.
// Tiles: A [rows][40] halves (80B rows), B [rows][40]. Offsets in elements.
__device__ __forceinline__ void mma_step(u32 aH, u32 aL, u32 bH, u32 bL,
                                         int mOff, int nOff, int kOff, int lane,
                                         float c[2][4][4]) {
    u32 ah[2][4], al[2][4];
    const int ar = lane & 15, ac = (lane >> 4) << 3;
#pragma unroll
    for (int mi = 0; mi < 2; mi++) {
        u32 off = (u32)(((mOff + mi * 16 + ar) * 40 + kOff + ac) * 2);
        ldsm4(aH + off, ah[mi][0], ah[mi][1], ah[mi][2], ah[mi][3]);
        ldsm4(aL + off, al[mi][0], al[mi][1], al[mi][2], al[mi][3]);
    }
    u32 bh[8], bl[8];
    const int g = lane >> 3;
    const int bn = ((g >> 1) << 3) + (lane & 7);
    const int bk = (g & 1) << 3;
#pragma unroll
    for (int hf = 0; hf < 2; hf++) {
        u32 off = (u32)(((nOff + hf * 16 + bn) * 40 + kOff + bk) * 2);
        ldsm4(bH + off, bh[hf*4+0], bh[hf*4+1], bh[hf*4+2], bh[hf*4+3]);
        ldsm4(bL + off, bl[hf*4+0], bl[hf*4+1], bl[hf*4+2], bl[hf*4+3]);
    }
#pragma unroll
    for (int mi = 0; mi < 2; mi++)
#pragma unroll
        for (int j = 0; j < 4; j++) {
            mma16816(c[mi][j], ah[mi][0], ah[mi][1], ah[mi][2], ah[mi][3], bh[j*2], bh[j*2+1]);
            mma16816(c[mi][j], ah[mi][0], ah[mi][1], ah[mi][2], ah[mi][3], bl[j*2], bl[j*2+1]);
            mma16816(c[mi][j], al[mi][0], al[mi][1], al[mi][2], al[mi][3], bh[j*2], bh[j*2+1]);
        }
}

// Write 2x4 m16n8 accumulators into smem tile T[TMrows][TLD]
__device__ __forceinline__ void frags_to_T(float* T, int TLD, int mW, int nW, int lane,
                                           float c[2][4][4]) {
    const int tq = lane >> 2, tc = (lane & 3) * 2;
#pragma unroll
    for (int mi = 0; mi < 2; mi++)
#pragma unroll
        for (int j = 0; j < 4; j++) {
            int rr = mW + mi * 16 + tq;
            int cc = nW + j * 8 + tc;
            T[rr * TLD + cc]     = c[mi][j][0];
            T[rr * TLD + cc + 1] = c[mi][j][1];
            T[(rr + 8) * TLD + cc]     = c[mi][j][2];
            T[(rr + 8) * TLD + cc + 1] = c[mi][j][3];
        }
}

// ---------------- prep: transpose+split [C][HW] fp32 -> [HW][C] fp16 planes ----------------
__global__ void tsplit_k(const float* __restrict__ in, __half* __restrict__ oh,
                         __half* __restrict__ ol) {
    __shared__ float t[32][33];
    const int b = blockIdx.z, x0 = blockIdx.x << 5, y0 = blockIdx.y << 5;
    const int tx = threadIdx.x, ty = threadIdx.y;
    const float* ib = in + (ll)b * CC * HWP;
#pragma unroll
    for (int i = 0; i < 32; i += 8)
        t[ty + i][tx] = ib[(ll)(y0 + ty + i) * HWP + x0 + tx];
    __syncthreads();
    const ll ob = (ll)b * HWP * CC;
#pragma unroll
    for (int i = 0; i < 32; i += 8) {
        __half h, l; h16(t[tx][ty + i], h, l);
        ll o = ob + (ll)(x0 + ty + i) * CC + y0 + tx;
        oh[o] = h; ol[o] = l;
    }
}

// weights: w[co][ci][kp] -> planes [co][kp*192+ci]
__global__ __launch_bounds__(256)
void wsplit_k(const float* __restrict__ w, __half* __restrict__ oh, __half* __restrict__ ol) {
    int t = blockIdx.x * 256 + threadIdx.x;
    if (t >= CC * KIMP) return;
    int co = t / KIMP, rem = t % KIMP, kp = rem / CC, ci = rem % CC;
    __half h, l; h16(w[((ll)co * CC + ci) * 9 + kp], h, l);
    oh[t] = h; ol[t] = l;
}

// ===========================================================================
// gc: conv GEMM (implicit im2col). C[co][p] = sum_k w'[co][k] * col[p][k].
//  A: weight planes [192][1728] (K order kp*192+ci). B: implicit from X planes [p][C].
//  TM=64 (co), TN=128 (p), KC=32, NC=54. 8 warps (2m x 4n).
//  MODE 1: bias+leaky -> planes OH/OL [p][C].  MODE 2: +resid(fp32 [C][HW]) -> planes.
// ===========================================================================
template<int MODE>
__global__ __launch_bounds__(256, 2)
void gc(const __half* __restrict__ Awh, const __half* __restrict__ Awl,
        const __half* __restrict__ Xh_, const __half* __restrict__ Xl_, ll xbat,
        const float* __restrict__ bias, const float* __restrict__ resid, ll rbat,
        __half* __restrict__ OH, __half* __restrict__ OL, ll obat)
{
    constexpr int AEL = 64 * 40, BEL = 128 * 40;
    constexpr int STEL = 2 * (AEL + BEL);      // 15360 halves / stage
    constexpr int TLD = 132;

    extern __shared__ float sm[];
    __half* smh = reinterpret_cast<__half*>(sm);
    const u32 sb = su32(smh);
    const int tid = threadIdx.x, w = tid >> 5, lane = tid & 31;
    const int mW = (w & 1) * 32, nW = (w >> 1) * 32;
    const int n0 = blockIdx.x * 128, m0 = blockIdx.y * 64, b = blockIdx.z;

    const __half* Xh = Xh_ + (ll)b * xbat;
    const __half* Xl = Xl_ + (ll)b * xbat;
    const int NC = KIMP / 32;   // 54

    uint4 rah, ral, rbh[2], rbl[2];
    auto fetch = [&](int c) {
        {   int r = tid >> 2, u = tid & 3;
            ll a = (ll)(m0 + r) * KIMP + c * 32 + u * 8;
            rah = *reinterpret_cast<const uint4*>(Awh + a);
            ral = *reinterpret_cast<const uint4*>(Awl + a);
        }
        const int kp = c / 6, ci0 = (c % 6) << 5;
        const int kh = kp / 3 - 1, kw = kp % 3 - 1;
#pragma unroll
        for (int i = 0; i < 2; i++) {
            int it = tid + i * 256;
            int r = it >> 2, u = it & 3;
            int p = n0 + r;
            int pr = (p >> 6) + kh, pc = (p & 63) + kw;
            uint4 vh = make_uint4(0,0,0,0), vl = vh;
            if (pr >= 0 && pr < 64 && pc >= 0 && pc < 64) {
                ll a = (ll)((pr << 6) + pc) * CC + ci0 + u * 8;
                vh = *reinterpret_cast<const uint4*>(Xh + a);
                vl = *reinterpret_cast<const uint4*>(Xl + a);
            }
            rbh[i] = vh; rbl[i] = vl;
        }
    };
    auto stash = [&](int s) {
        __half* A_h = smh + s * STEL;  __half* A_l = A_h + AEL;
        __half* B_h = A_l + AEL;       __half* B_l = B_h + BEL;
        {   int r = tid >> 2, u = tid & 3;
            int o = r * 40 + u * 8;
            *reinterpret_cast<uint4*>(A_h + o) = rah;
            *reinterpret_cast<uint4*>(A_l + o) = ral;
        }
#pragma unroll
        for (int i = 0; i < 2; i++) {
            int it = tid + i * 256;
            int r = it >> 2, u = it & 3;
            int o = r * 40 + u * 8;
            *reinterpret_cast<uint4*>(B_h + o) = rbh[i];
            *reinterpret_cast<uint4*>(B_l + o) = rbl[i];
        }
    };

    float acc[2][4][4];
#pragma unroll
    for (int mi = 0; mi < 2; mi++)
#pragma unroll
        for (int j = 0; j < 4; j++)
#pragma unroll
            for (int e = 0; e < 4; e++) acc[mi][j][e] = 0.f;

    fetch(0); stash(0); __syncthreads();
    for (int c = 0; c < NC; c++) {
        const bool more = (c + 1 < NC);
        if (more) fetch(c + 1);
        const u32 st = sb + (u32)((c & 1) * STEL * 2);
        const u32 aH = st, aL = st + AEL * 2, bH = aL + AEL * 2, bL = bH + BEL * 2;
        mma_step(aH, aL, bH, bL, mW, nW, 0,  lane, acc);
        mma_step(aH, aL, bH, bL, mW, nW, 16, lane, acc);
        if (more) stash((c + 1) & 1);
        __syncthreads();
    }

    float* T = sm;
    frags_to_T(T, TLD, mW, nW, lane, acc);
    __syncthreads();

    // epilogue: tile is [co(64)][p(128)]; iterate co-fast for coalesced plane writes
    for (int idx = tid; idx < 64 * 128; idx += 256) {
        int pi = idx >> 6, coi = idx & 63;
        float v = T[coi * TLD + pi] + bias[m0 + coi];
        v = v > 0.f ? v : LEAK * v;
        if (MODE == 2)
            v += resid[(ll)b * rbat + (ll)(m0 + coi) * HWP + n0 + pi];
        __half h, l; h16(v, h, l);
        ll o = (ll)b * obat + (ll)(n0 + pi) * CC + m0 + coi;
        OH[o] = h; OL[o] = l;
    }
}

// ===========================================================================
// gx: corr[q][r] = sum_c f1[q][c] * f2[r][c].  A,B: planes [p][C]. K=192.
//  TM=64 (q), TN=128 (r), KC=32, NC=6.
// ===========================================================================
__global__ __launch_bounds__(256, 2)
void gx(const __half* __restrict__ Ah_, const __half* __restrict__ Al_,
        const __half* __restrict__ Bh_, const __half* __restrict__ Bl_,
        float* __restrict__ C)
{
    constexpr int AEL = 64 * 40, BEL = 128 * 40;
    constexpr int STEL = 2 * (AEL + BEL);
    constexpr int TLD = 132;

    extern __shared__ float sm[];
    __half* smh = reinterpret_cast<__half*>(sm);
    const u32 sb = su32(smh);
    const int tid = threadIdx.x, w = tid >> 5, lane = tid & 31;
    const int mW = (w & 1) * 32, nW = (w >> 1) * 32;
    const int n0 = blockIdx.x * 128, m0 = blockIdx.y * 64, b = blockIdx.z;

    const __half* Ah = Ah_ + (ll)b * (HWP * CC);
    const __half* Al = Al_ + (ll)b * (HWP * CC);
    const __half* Bh = Bh_ + (ll)b * (HWP * CC);
    const __half* Bl = Bl_ + (ll)b * (HWP * CC);

    uint4 rah, ral, rbh[2], rbl[2];
    auto fetch = [&](int c) {
        {   int r = tid >> 2, u = tid & 3;
            ll a = (ll)(m0 + r) * CC + c * 32 + u * 8;
            rah = *reinterpret_cast<const uint4*>(Ah + a);
            ral = *reinterpret_cast<const uint4*>(Al + a);
        }
#pragma unroll
        for (int i = 0; i < 2; i++) {
            int it = tid + i * 256;
            int r = it >> 2, u = it & 3;
            ll a = (ll)(n0 + r) * CC + c * 32 + u * 8;
            rbh[i] = *reinterpret_cast<const uint4*>(Bh + a);
            rbl[i] = *reinterpret_cast<const uint4*>(Bl + a);
        }
    };
    auto stash = [&](int s) {
        __half* A_h = smh + s * STEL;  __half* A_l = A_h + AEL;
        __half* B_h = A_l + AEL;       __half* B_l = B_h + BEL;
        {   int r = tid >> 2, u = tid & 3;
            int o = r * 40 + u * 8;
            *reinterpret_cast<uint4*>(A_h + o) = rah;
            *reinterpret_cast<uint4*>(A_l + o) = ral;
        }
#pragma unroll
        for (int i = 0; i < 2; i++) {
            int it = tid + i * 256;
            int r = it >> 2, u = it & 3;
            int o = r * 40 + u * 8;
            *reinterpret_cast<uint4*>(B_h + o) = rbh[i];
            *reinterpret_cast<uint4*>(B_l + o) = rbl[i];
        }
    };

    float acc[2][4][4];
#pragma unroll
    for (int mi = 0; mi < 2; mi++)
#pragma unroll
        for (int j = 0; j < 4; j++)
#pragma unroll
            for (int e = 0; e < 4; e++) acc[mi][j][e] = 0.f;

    fetch(0); stash(0); __syncthreads();
    for (int c = 0; c < 6; c++) {
        const bool more = (c + 1 < 6);
        if (more) fetch(c + 1);
        const u32 st = sb + (u32)((c & 1) * STEL * 2);
        const u32 aH = st, aL = st + AEL * 2, bH = aL + AEL * 2, bL = bH + BEL * 2;
        mma_step(aH, aL, bH, bL, mW, nW, 0,  lane, acc);
        mma_step(aH, aL, bH, bL, mW, nW, 16, lane, acc);
        if (more) stash((c + 1) & 1);
        __syncthreads();
    }

    float* T = sm;
    frags_to_T(T, TLD, mW, nW, lane, acc);
    __syncthreads();

    float* Cb = C + (ll)b * ((ll)HWP * HWP);
    for (int idx = tid; idx < 64 * 32; idx += 256) {   // float4 granularity
        int row = idx >> 5, q4 = idx & 31;
        float4 v = make_float4(T[row * TLD + q4 * 4], T[row * TLD + q4 * 4 + 1],
                               T[row * TLD + q4 * 4 + 2], T[row * TLD + q4 * 4 + 3]);
        *reinterpret_cast<float4*>(Cb + (ll)(m0 + row) * HWP + n0 + q4 * 4) = v;
    }
}

// ===========================================================================
// ga: C[n][m] = sum_k A(m,k)*B(n,k), TRANSPOSED store.
//  A: corr [M][K] fp32. B: ref [N][K] fp32. TM=128, TN=64, KC=32. In-loop split.
// ===========================================================================
__global__ __launch_bounds__(256, 2)
void ga(const float* __restrict__ A, ll abat, int lda,
        const float* __restrict__ B, ll bbat, int ldb,
        int K, float* __restrict__ C, ll cbat, int ldc)
{
    constexpr int AEL = 128 * 40, BEL = 64 * 40;
    constexpr int STEL = 2 * (AEL + BEL);
    constexpr int TLD = 68;

    extern __shared__ float sm[];
    __half* smh = reinterpret_cast<__half*>(sm);
    const u32 sb = su32(smh);
    const int tid = threadIdx.x, w = tid >> 5, lane = tid & 31;
    const int mW = (w & 3) * 32, nW = (w >> 2) * 32;
    const int n0 = blockIdx.x * 64, m0 = blockIdx.y * 128, b = blockIdx.z;

    const float* Ab = A + (ll)b * abat;
    const float* Bb = B + (ll)b * bbat;
    const int NC = K >> 5;

    float4 ra[4], rb[2];
    auto fetch = [&](int c) {
#pragma unroll
        for (int i = 0; i < 4; i++) {
            int it = tid + i * 256;
            int r = it >> 3, u = it & 7;
            ra[i] = *reinterpret_cast<const float4*>(Ab + (ll)(m0 + r) * lda + c * 32 + u * 4);
        }
#pragma unroll
        for (int i = 0; i < 2; i++) {
            int it = tid + i * 256;
            int r = it >> 3, u = it & 7;
            rb[i] = *reinterpret_cast<const float4*>(Bb + (ll)(n0 + r) * ldb + c * 32 + u * 4);
        }
    };
    auto put4 = [](__half* H, __half* L, int o, float4 v) {
        __half h0, l0, h1, l1, h2, l2, h3, l3;
        h16(v.x, h0, l0); h16(v.y, h1, l1); h16(v.z, h2, l2); h16(v.w, h3, l3);
        __half2* hp = reinterpret_cast<__half2*>(H + o);
        __half2* lp = reinterpret_cast<__half2*>(L + o);
        hp[0] = __halves2half2(h0, h1); hp[1] = __halves2half2(h2, h3);
        lp[0] = __halves2half2(l0, l1); lp[1] = __halves2half2(l2, l3);
    };
    auto stash = [&](int s) {
        __half* A_h = smh + s * STEL;  __half* A_l = A_h + AEL;
        __half* B_h = A_l + AEL;       __half* B_l = B_h + BEL;
#pragma unroll
        for (int i = 0; i < 4; i++) {
            int it = tid + i * 256;
            int r = it >> 3, u = it & 7;
            put4(A_h, A_l, r * 40 + u * 4, ra[i]);
        }
#pragma unroll
        for (int i = 0; i < 2; i++) {
            int it = tid + i * 256;
            int r = it >> 3, u = it & 7;
            put4(B_h, B_l, r * 40 + u * 4, rb[i]);
        }
    };

    float acc[2][4][4];
#pragma unroll
    for (int mi = 0; mi < 2; mi++)
#pragma unroll
        for (int j = 0; j < 4; j++)
#pragma unroll
            for (int e = 0; e < 4; e++) acc[mi][j][e] = 0.f;

    fetch(0); stash(0); __syncthreads();
    for (int c = 0; c < NC; c++) {
        const bool more = (c + 1 < NC);
        if (more) fetch(c + 1);
        const u32 st = sb + (u32)((c & 1) * STEL * 2);
        const u32 aH = st, aL = st + AEL * 2, bH = aL + AEL * 2, bL = bH + BEL * 2;
        mma_step(aH, aL, bH, bL, mW, nW, 0,  lane, acc);
        mma_step(aH, aL, bH, bL, mW, nW, 16, lane, acc);
        if (more) stash((c + 1) & 1);
        __syncthreads();
    }

    float* T = sm;
    frags_to_T(T, TLD, mW, nW, lane, acc);
    __syncthreads();

    for (int idx = tid; idx < 128 * 64; idx += 256) {
        int row = idx & 127, col = idx >> 7;    // row = pixel (fast), col = channel
        C[(ll)b * cbat + (ll)(n0 + col) * ldc + m0 + row] = T[row * TLD + col];
    }
}

// ---------------- softmax (proven) ----------------
__device__ __forceinline__ float wmaxf(float v) {
#pragma unroll
    for (int o = 16; o > 0; o >>= 1) v = fmaxf(v, __shfl_xor_sync(0xffffffffu, v, o));
    return v;
}
__device__ __forceinline__ float wsumf(float v) {
#pragma unroll
    for (int o = 16; o > 0; o >>= 1) v += __shfl_xor_sync(0xffffffffu, v, o);
    return v;
}
__global__ __launch_bounds__(256)
void softmax4_k(float* __restrict__ S) {
    float4* p = reinterpret_cast<float4*>(S + (ll)blockIdx.x * HWP);
    const int tid = threadIdx.x;
    const int lane = tid & 31, wid = tid >> 5;
    float4 v[4]; float mx = -3.0e38f;
#pragma unroll
    for (int i = 0; i < 4; i++) {
        v[i] = p[tid + 256 * i];
        mx = fmaxf(mx, fmaxf(fmaxf(v[i].x, v[i].y), fmaxf(v[i].z, v[i].w)));
    }
    __shared__ float red[8];
    mx = wmaxf(mx);
    if (lane == 0) red[wid] = mx;
    __syncthreads();
    if (wid == 0) { float t = (lane < 8) ? red[lane] : -3.0e38f; t = wmaxf(t); if (lane == 0) red[0] = t; }
    __syncthreads();
    mx = red[0];
    __syncthreads();
    float s = 0.f;
#pragma unroll
    for (int i = 0; i < 4; i++) {
        v[i].x = __expf(v[i].x - mx); v[i].y = __expf(v[i].y - mx);
        v[i].z = __expf(v[i].z - mx); v[i].w = __expf(v[i].w - mx);
        s += v[i].x + v[i].y + v[i].z + v[i].w;
    }
    s = wsumf(s);
    if (lane == 0) red[wid] = s;
    __syncthreads();
    if (wid == 0) { float t = (lane < 8) ? red[lane] : 0.f; t = wsumf(t); if (lane == 0) red[0] = t; }
    __syncthreads();
    const float inv = 1.f / red[0];
#pragma unroll
    for (int i = 0; i < 4; i++) {
        v[i].x *= inv; v[i].y *= inv; v[i].z *= inv; v[i].w *= inv;
        p[tid + 256 * i] = v[i];
    }
}

// ---------------- pool (proven) ----------------
__global__ __launch_bounds__(256)
void pool2_k(const float* __restrict__ in, float* __restrict__ out, int g) {
    const int g2 = g >> 1;
    const int G2 = g2 * g2;
    const int halfP = G2 >> 1;
    const ll total = (ll)BB * G2 * halfP;
    ll idx = (ll)blockIdx.x * 256 + threadIdx.x;
    if (idx >= total) return;
    int t  = (int)(idx % halfP);
    int qp = (int)((idx / halfP) % G2);
    int b  = (int)(idx / ((ll)halfP * G2));
    const int Rh  = (2 * t) / g2;
    const int Rw0 = (2 * t) % g2;
    const int Qh = qp / g2, Qw = qp % g2;
    const ll G = (ll)g * g;
    const float* base = in + (ll)b * G * G;
    float s0 = 0.f, s1 = 0.f;
#pragma unroll
    for (int i = 0; i < 2; i++)
#pragma unroll
        for (int j = 0; j < 2; j++) {
            const float* qrow = base + ((ll)((2 * Qh + i) * g + 2 * Qw + j)) * G;
#pragma unroll
            for (int u = 0; u < 2; u++) {
                const float2* rp = reinterpret_cast<const float2*>(
                    qrow + (ll)(2 * Rh + u) * g + 2 * Rw0);
                float2 x0 = rp[0], x1 = rp[1];
                s0 += x0.x + x0.y;
                s1 += x1.x + x1.y;
            }
        }
    float2 o = make_float2(s0 * (1.f / 16.f), s1 * (1.f / 16.f));
    *reinterpret_cast<float2*>(out + ((ll)b * G2 + qp) * G2 + 2 * t) = o;
}

// ---------------- host ----------------
#define GS(p, s) cudaGetSymbolAddress((void**)&p, s)

extern "C" void kernel_launch(void* const* d_in, const int* in_sizes, int n_in,
                              void* d_out, int out_size)
{
    const float* fd1 = (const float*)d_in[0];
    const float* fd2 = (const float*)d_in[1];
    const float* ref = (const float*)d_in[2];
    const float* o1  = (const float*)d_in[3];
    const float* o2  = (const float*)d_in[4];
    const float* tw1 = (const float*)d_in[5];
    const float* tb1 = (const float*)d_in[6];
    const float* tw2 = (const float*)d_in[7];
    const float* tb2 = (const float*)d_in[8];
    const float* pw1 = (const float*)d_in[9];
    const float* pb1 = (const float*)d_in[10];
    const float* pw2 = (const float*)d_in[11];
    const float* pb2 = (const float*)d_in[12];
    float* out = (float*)d_out;

    __half *x1h, *x1l, *x2h, *x2l, *th, *tl, *f1h, *f1l, *f2h, *f2l;
    __half *wbh, *wbl;
    float *corr, *corr1, *corr2;
    GS(x1h, g_x1h); GS(x1l, g_x1l); GS(x2h, g_x2h); GS(x2l, g_x2l);
    GS(th, g_th); GS(tl, g_tl);
    GS(f1h, g_f1h); GS(f1l, g_f1l); GS(f2h, g_f2h); GS(f2l, g_f2l);
    GS(wbh, g_wallh); GS(wbl, g_walll);
    GS(corr, g_corr); GS(corr1, g_corr1); GS(corr2, g_corr2);

    const size_t WSTR = (size_t)CC * KIMP;
    __half* w0h = wbh;            __half* w0l = wbl;
    __half* w1h = wbh + WSTR;     __half* w1l = wbl + WSTR;
    __half* w2h = wbh + 2 * WSTR; __half* w2l = wbl + 2 * WSTR;
    __half* w3h = wbh + 3 * WSTR; __half* w3l = wbl + 3 * WSTR;

    const int SMEM = 61440;   // 2 stages x 15360 halves
    cudaFuncSetAttribute(gc<1>, cudaFuncAttributeMaxDynamicSharedMemorySize, SMEM);
    cudaFuncSetAttribute(gc<2>, cudaFuncAttributeMaxDynamicSharedMemorySize, SMEM);
    cudaFuncSetAttribute(gx,    cudaFuncAttributeMaxDynamicSharedMemorySize, SMEM);
    cudaFuncSetAttribute(ga,    cudaFuncAttributeMaxDynamicSharedMemorySize, SMEM);

    const ll featB = (ll)HWP * CC;     // plane batch stride
    const ll refB  = (ll)CC * HWP;
    const int wGrid = (CC * KIMP + 255) / 256;
    const dim3 convG(32, 3, BB);

    // prep
    {
        dim3 g(HWP / 32, CC / 32, BB), blk(32, 8);
        tsplit_k<<<g, blk>>>(fd1, x1h, x1l);
        tsplit_k<<<g, blk>>>(fd2, x2h, x2l);
    }
    wsplit_k<<<wGrid, 256>>>(tw1, w0h, w0l);
    wsplit_k<<<wGrid, 256>>>(tw2, w1h, w1l);
    wsplit_k<<<wGrid, 256>>>(pw1, w2h, w2l);
    wsplit_k<<<wGrid, 256>>>(pw2, w3h, w3l);

    // theta resblock
    gc<1><<<convG, 256, SMEM>>>(w0h, w0l, x1h, x1l, featB, tb1, nullptr, 0, th, tl, featB);
    gc<2><<<convG, 256, SMEM>>>(w1h, w1l, th, tl, featB, tb2, fd1, refB, f1h, f1l, featB);
    // phi resblock
    gc<1><<<convG, 256, SMEM>>>(w2h, w2l, x2h, x2l, featB, pb1, nullptr, 0, th, tl, featB);
    gc<2><<<convG, 256, SMEM>>>(w3h, w3l, th, tl, featB, pb2, fd2, refB, f2h, f2l, featB);

    // corr = f1 f2^T
    gx<<<dim3(32, 64, BB), 256, SMEM>>>(f1h, f1l, f2h, f2l, corr);
    softmax4_k<<<BB * HWP, 256>>>(corr);

    // out0: A=corr [q][r], B=ref [c][r] -> [c][q]
    ga<<<dim3(3, 32, BB), 256, SMEM>>>(corr, (ll)HWP * HWP, HWP,
        ref, refB, HWP, HWP, out, refB, HWP);

    // level 1
    {
        const ll total = (ll)BB * 1024 * 512;
        pool2_k<<<(int)((total + 255) / 256), 256>>>(corr, corr1, 64);
        ga<<<dim3(3, 8, BB), 256, SMEM>>>(corr1, (ll)1024 * 1024, 1024,
            o1, (ll)CC * 1024, 1024, 1024,
            out + (ll)BB * refB, (ll)CC * 1024, 1024);
    }
    // level 2
    {
        const ll total = (ll)BB * 256 * 128;
        pool2_k<<<(int)((total + 255) / 256), 256>>>(corr1, corr2, 32);
        ga<<<dim3(3, 2, BB), 256, SMEM>>>(corr2, (ll)256 * 256, 256,
            o2, (ll)CC * 256, 256, 256,
            out + (ll)BB * refB + (ll)BB * CC * 1024, (ll)CC * 256, 256);
    }

    (void)in_sizes; (void)n_in; (void)out_size;
}